// round 17
// baseline (speedup 1.0000x reference)
#include <cuda_runtime.h>
#include <cuda_bf16.h>
#include <cstdint>

// Two-simplicial attention via mma.sync.m16n8k16 bf16 split-fp32.
// One position per CTA, 256 threads (8 warps), 4 CTAs/SM.
// R17 = R16 - V1F smem buffer (v1 read from global/L2 in epilogue B)
//       -> 56.4 KB smem -> 4 CTAs/SM.

constexpr int Sc = 2048, Hc = 4, Dc = 64;
constexpr float QSCALE = 0.125f * 1.4426950408889634f;  // SCALE * log2(e)
constexpr int NT = 256;

// ---- smem byte offsets (bf16 tiles: row stride 72 elems = 144 B) ----
// A3H/A3L hold 65 real rows; ldmatrix tail reads (rows 65..79) spill into the
// following buffer as masked garbage (proven safe R14-R16).
constexpr int OFF_A3H   = 0;         // [65+][72] bf16  k1q hi (reused as W hi)
constexpr int OFF_A3L   = 9360;      // [65+][72] bf16  k1q lo (reused as W lo)
constexpr int OFF_B3H   = 18720;     // [64][72] bf16  k2 hi   rows=c, cols=d
constexpr int OFF_B3L   = 27936;
constexpr int OFF_B4H   = 37152;     // [64][72] bf16  v2 hi   rows=c, cols=d
constexpr int OFF_B4L   = 46368;
constexpr int OFF_K2R64 = 55584;     // f32 [64]
constexpr int OFF_V2R64 = 55840;     // f32 [64]
constexpr int OFF_WC64  = 56096;     // f32 [65]
constexpr int OFF_DEN   = 56356;     // f32 [8]
constexpr int OFF_OST   = OFF_B3H;   // f32 [16][68] aliased onto dead B3H
constexpr int SMEM_BYTES = 56448;    // x4 CTAs = 225.8 KB <= 228 KB

constexpr int LD_A = OFF_A3L - OFF_A3H;   // 9360
constexpr int LD_B = OFF_B3L - OFF_B3H;   // 9216

__device__ __forceinline__ uint32_t smem_u32(const void* p) {
    uint32_t a;
    asm("{ .reg .u64 t; cvta.to.shared.u64 t, %1; cvt.u32.u64 %0, t; }" : "=r"(a) : "l"(p));
    return a;
}
__device__ __forceinline__ uint32_t bf2(float lo, float hi) {
    uint32_t r;
    asm("cvt.rn.bf16x2.f32 %0, %1, %2;" : "=r"(r) : "f"(hi), "f"(lo));
    return r;
}
__device__ __forceinline__ void split2(float x0, float x1, uint32_t& h, uint32_t& l) {
    h = bf2(x0, x1);
    float h0 = __uint_as_float(h << 16);
    float h1 = __uint_as_float(h & 0xFFFF0000u);
    l = bf2(x0 - h0, x1 - h1);
}
__device__ __forceinline__ float rlo(uint32_t w) { return __uint_as_float(w << 16); }
__device__ __forceinline__ float rhi(uint32_t w) { return __uint_as_float(w & 0xFFFF0000u); }
__device__ __forceinline__ void ldsm4(uint32_t& r0, uint32_t& r1, uint32_t& r2,
                                      uint32_t& r3, uint32_t a) {
    asm volatile("ldmatrix.sync.aligned.m8n8.x4.shared.b16 {%0,%1,%2,%3}, [%4];"
                 : "=r"(r0), "=r"(r1), "=r"(r2), "=r"(r3) : "r"(a));
}
__device__ __forceinline__ void ldsm4t(uint32_t& r0, uint32_t& r1, uint32_t& r2,
                                       uint32_t& r3, uint32_t a) {
    asm volatile("ldmatrix.sync.aligned.m8n8.x4.trans.shared.b16 {%0,%1,%2,%3}, [%4];"
                 : "=r"(r0), "=r"(r1), "=r"(r2), "=r"(r3) : "r"(a));
}
__device__ __forceinline__ void mma16816(float* d, const uint32_t* a, const uint32_t* b) {
    asm volatile(
        "mma.sync.aligned.m16n8k16.row.col.f32.bf16.bf16.f32 "
        "{%0,%1,%2,%3}, {%4,%5,%6,%7}, {%8,%9}, {%0,%1,%2,%3};"
        : "+f"(d[0]), "+f"(d[1]), "+f"(d[2]), "+f"(d[3])
        : "r"(a[0]), "r"(a[1]), "r"(a[2]), "r"(a[3]), "r"(b[0]), "r"(b[1]));
}

__global__ void __launch_bounds__(NT, 4)
tsa_kernel(const float* __restrict__ q,
           const float* __restrict__ k1,
           const float* __restrict__ k2,
           const float* __restrict__ v1,
           const float* __restrict__ v2,
           float* __restrict__ out) {
    extern __shared__ __align__(1024) char smem[];
    const int tid = threadIdx.x;
    const int wid = tid >> 5, lane = tid & 31;
    const int wm = wid & 1;          // m-group: tiles {0,1,2} or {3,4}
    const int wn = wid >> 1;         // n-group: 2 n-tiles each
    const int nti = 3 - wm;          // m-tiles owned by this warp
    const int bid = blockIdx.x;
    const int h = bid & 3;
    const int s = (bid >> 2) & 2047;
    const int b = bid >> 13;
    const int amin = 64 - s;
    const uint32_t smb = smem_u32(smem);

    // ================= prologue =================
    const int qb = ((b * Sc + s) * Hc + h) * Dc;
    const int dq = tid & 15;
    float4 qv = *(const float4*)&q[qb + dq * 4];
    qv.x *= QSCALE; qv.y *= QSCALE; qv.z *= QSCALE; qv.w *= QSCALE;

    for (int i = tid; i < 65 * 16; i += NT) {
        int r = i >> 4;
        int g = s - 64 + r; if (g < 0) g = 0;
        int off = ((b * Sc + g) * Hc + h) * Dc + dq * 4;

        float4 kv = *(const float4*)&k1[off];
        kv.x *= qv.x; kv.y *= qv.y; kv.z *= qv.z; kv.w *= qv.w;
        {
            uint32_t h01, l01, h23, l23;
            split2(kv.x, kv.y, h01, l01);
            split2(kv.z, kv.w, h23, l23);
            *(uint2*)(smem + OFF_A3H + r * 144 + dq * 8) = make_uint2(h01, h23);
            *(uint2*)(smem + OFF_A3L + r * 144 + dq * 8) = make_uint2(l01, l23);
        }
        float4 cv = *(const float4*)&k2[off];
        if (r < 64) {
            uint32_t h01, l01, h23, l23;
            split2(cv.x, cv.y, h01, l01);
            split2(cv.z, cv.w, h23, l23);
            *(uint2*)(smem + OFF_B3H + r * 144 + dq * 8) = make_uint2(h01, h23);
            *(uint2*)(smem + OFF_B3L + r * 144 + dq * 8) = make_uint2(l01, l23);
        } else {
            *(float4*)(smem + OFF_K2R64 + dq * 16) = cv;
        }
        float4 vv = *(const float4*)&v2[off];
        if (r < 64) {
            uint32_t h01, l01, h23, l23;
            split2(vv.x, vv.y, h01, l01);
            split2(vv.z, vv.w, h23, l23);
            *(uint2*)(smem + OFF_B4H + r * 144 + dq * 8) = make_uint2(h01, h23);
            *(uint2*)(smem + OFF_B4L + r * 144 + dq * 8) = make_uint2(l01, l23);
        } else {
            *(float4*)(smem + OFF_V2R64 + dq * 16) = vv;
        }
    }
    __syncthreads();

    // fragment addresses
    const int arow = (lane & 7) + 8 * ((lane >> 3) & 1);
    const int acol = 8 * (lane >> 4);
    const uint32_t aoffs = arow * 144 + acol * 2;          // + T*16*144 + k*32
    const uint32_t b3base = smb + OFF_B3H
        + ((wn * 2 + (lane >> 4)) * 8 + (lane & 7)) * 144
        + ((lane >> 3) & 1) * 16;                          // + k*32
    const uint32_t b4base = smb + OFF_B4H
        + (((lane >> 3) & 1) * 8 + (lane & 7)) * 144
        + (wn * 2 + (lane >> 4)) * 16;                     // + k*2304

    // ================= phase 3: scores via MMA (pre-scaled, log2 domain) =========
    float acc[3][2][4];
#pragma unroll
    for (int i = 0; i < 3; i++)
#pragma unroll
        for (int j = 0; j < 2; j++)
#pragma unroll
            for (int e = 0; e < 4; e++) acc[i][j][e] = 0.0f;

#pragma unroll
    for (int k = 0; k < 4; k++) {
        uint32_t bh[2][2], bl[2][2];
        ldsm4(bh[0][0], bh[0][1], bh[1][0], bh[1][1], b3base + k * 32);
        ldsm4(bl[0][0], bl[0][1], bl[1][0], bl[1][1], b3base + LD_B + k * 32);
#pragma unroll
        for (int i = 0; i < 3; i++) {
            if (i < nti) {
                uint32_t ah[4], al[4];
                uint32_t aa = smb + OFF_A3H + aoffs + (wm * 3 + i) * 16 * 144 + k * 32;
                ldsm4(ah[0], ah[1], ah[2], ah[3], aa);
                ldsm4(al[0], al[1], al[2], al[3], aa + LD_A);
#pragma unroll
                for (int j = 0; j < 2; j++) {
                    mma16816(acc[i][j], ah, bh[j]);
                    mma16816(acc[i][j], ah, bl[j]);
                    mma16816(acc[i][j], al, bh[j]);
                }
            }
        }
    }

    // ---- c = 64 score column (f32 SIMT, k1q reconstructed from bf16 tiles) ----
    float dloc = 0.0f;
    if (tid < 65) {
        const char* rowH = smem + OFF_A3H + tid * 144;
        const char* rowL = smem + OFF_A3L + tid * 144;
        const float* k2r = (const float*)(smem + OFF_K2R64);
        float a0 = 0.f, a1 = 0.f;
#pragma unroll
        for (int j = 0; j < 8; j++) {
            uint4 hh = *(const uint4*)(rowH + j * 16);
            uint4 ll = *(const uint4*)(rowL + j * 16);
            const float* kr = k2r + j * 8;
            a0 = fmaf(rlo(hh.x) + rlo(ll.x), kr[0], a0);
            a1 = fmaf(rhi(hh.x) + rhi(ll.x), kr[1], a1);
            a0 = fmaf(rlo(hh.y) + rlo(ll.y), kr[2], a0);
            a1 = fmaf(rhi(hh.y) + rhi(ll.y), kr[3], a1);
            a0 = fmaf(rlo(hh.z) + rlo(ll.z), kr[4], a0);
            a1 = fmaf(rhi(hh.z) + rhi(ll.z), kr[5], a1);
            a0 = fmaf(rlo(hh.w) + rlo(ll.w), kr[6], a0);
            a1 = fmaf(rhi(hh.w) + rhi(ll.w), kr[7], a1);
        }
        float w = (tid >= amin) ? exp2f(a0 + a1) : 0.0f;
        ((float*)(smem + OFF_WC64))[tid] = w;
        dloc += w;
    }
    __syncthreads();   // all warps done reading A3 (k1q) before W overwrites it

    // ================= epilogue A: mask+exp, W -> A-tile =================
    {
        const int rb = lane >> 2;
#pragma unroll
        for (int i = 0; i < 3; i++) {
            if (i < nti) {
                int r0 = (wm * 3 + i) * 16 + rb, r1 = r0 + 8;
                bool av0 = (r0 <= 64) && (r0 >= amin);
                bool av1 = (r1 <= 64) && (r1 >= amin);
#pragma unroll
                for (int j = 0; j < 2; j++) {
                    int c0 = (wn * 2 + j) * 8 + 2 * (lane & 3);
                    bool cv0 = (c0 >= amin), cv1 = (c0 + 1 >= amin);
                    float w0 = (av0 && cv0) ? exp2f(acc[i][j][0]) : 0.0f;
                    float w1 = (av0 && cv1) ? exp2f(acc[i][j][1]) : 0.0f;
                    float w2 = (av1 && cv0) ? exp2f(acc[i][j][2]) : 0.0f;
                    float w3 = (av1 && cv1) ? exp2f(acc[i][j][3]) : 0.0f;
                    dloc += (w0 + w1) + (w2 + w3);
                    if (r0 <= 64) {
                        uint32_t hh, ll;
                        split2(w0, w1, hh, ll);
                        *(uint32_t*)(smem + OFF_A3H + r0 * 144 + c0 * 2) = hh;
                        *(uint32_t*)(smem + OFF_A3L + r0 * 144 + c0 * 2) = ll;
                    }
                    if (r1 <= 64) {
                        uint32_t hh, ll;
                        split2(w2, w3, hh, ll);
                        *(uint32_t*)(smem + OFF_A3H + r1 * 144 + c0 * 2) = hh;
                        *(uint32_t*)(smem + OFF_A3L + r1 * 144 + c0 * 2) = ll;
                    }
                }
            }
        }
    }
#pragma unroll
    for (int o = 16; o; o >>= 1) dloc += __shfl_xor_sync(0xFFFFFFFFu, dloc, o);
    if (lane == 0) ((float*)(smem + OFF_DEN))[wid] = dloc;
    __syncthreads();   // W tile + WC64 + DEN visible

    // ================= phase 4: O = W @ V2 via MMA (trans B loads) =================
    float acc2[3][2][4];
#pragma unroll
    for (int i = 0; i < 3; i++)
#pragma unroll
        for (int j = 0; j < 2; j++)
#pragma unroll
            for (int e = 0; e < 4; e++) acc2[i][j][e] = 0.0f;

#pragma unroll
    for (int k = 0; k < 4; k++) {
        uint32_t bh[2][2], bl[2][2];
        ldsm4t(bh[0][0], bh[0][1], bh[1][0], bh[1][1], b4base + k * 2304);
        ldsm4t(bl[0][0], bl[0][1], bl[1][0], bl[1][1], b4base + LD_B + k * 2304);
#pragma unroll
        for (int i = 0; i < 3; i++) {
            if (i < nti) {
                uint32_t ah[4], al[4];
                uint32_t aa = smb + OFF_A3H + aoffs + (wm * 3 + i) * 16 * 144 + k * 32;
                ldsm4(ah[0], ah[1], ah[2], ah[3], aa);
                ldsm4(al[0], al[1], al[2], al[3], aa + LD_A);
#pragma unroll
                for (int j = 0; j < 2; j++) {
                    mma16816(acc2[i][j], ah, bh[j]);
                    mma16816(acc2[i][j], ah, bl[j]);
                    mma16816(acc2[i][j], al, bh[j]);
                }
            }
        }
    }

    // ================= epilogue B: +c64 term, v1 fold (global/L2), a-reduce =======
    {
        const int res = lane >> 2;
        const float* WC = (const float*)(smem + OFF_WC64);
        const float* V2R = (const float*)(smem + OFF_V2R64);
        const float* v1base = v1 + ((b * Sc) * Hc + h) * Dc;  // + g*256 + d
#pragma unroll
        for (int j = 0; j < 2; j++) {
            int d0 = (wn * 2 + j) * 8 + 2 * (lane & 3);
            float vr0 = V2R[d0], vr1 = V2R[d0 + 1];
            float s0 = 0.0f, s1 = 0.0f;
#pragma unroll
            for (int i = 0; i < 3; i++) {
                if (i < nti) {
#pragma unroll
                    for (int hf = 0; hf < 2; hf++) {
                        int a = (wm * 3 + i) * 16 + res + 8 * hf;
                        if (a <= 64) {
                            float wc = WC[a];
                            float o0 = acc2[i][j][2 * hf + 0] + wc * vr0;
                            float o1 = acc2[i][j][2 * hf + 1] + wc * vr1;
                            int g = s - 64 + a; if (g < 0) g = 0;
                            const float* vp = v1base + g * (Hc * Dc) + d0;
                            s0 += o0 * vp[0];
                            s1 += o1 * vp[1];
                        }
                    }
                }
            }
            ((float*)(smem + OFF_OST))[(wm * 8 + res) * 68 + d0] = s0;
            ((float*)(smem + OFF_OST))[(wm * 8 + res) * 68 + d0 + 1] = s1;
        }
    }
    __syncthreads();

    if (tid < 64) {
        const float* DEN = (const float*)(smem + OFF_DEN);
        const float* OST = (const float*)(smem + OFF_OST);
        float den = 1e-8f;
#pragma unroll
        for (int w = 0; w < 8; w++) den += DEN[w];
        float num = 0.0f;
#pragma unroll
        for (int r = 0; r < 16; r++) num += OST[r * 68 + tid];
        out[qb + tid] = num / den;
    }
}

extern "C" void kernel_launch(void* const* d_in, const int* in_sizes, int n_in,
                              void* d_out, int out_size) {
    const float* q  = (const float*)d_in[0];
    const float* k1 = (const float*)d_in[1];
    const float* k2 = (const float*)d_in[2];
    const float* v1 = (const float*)d_in[3];
    const float* v2 = (const float*)d_in[4];
    float* out = (float*)d_out;

    cudaFuncSetAttribute(tsa_kernel, cudaFuncAttributeMaxDynamicSharedMemorySize,
                         SMEM_BYTES);
    dim3 grid(2 * Sc * Hc);
    tsa_kernel<<<grid, NT, SMEM_BYTES>>>(q, k1, k2, v1, v2, out);
}